// round 13
// baseline (speedup 1.0000x reference)
#include <cuda_runtime.h>
#include <cuda_fp16.h>

// Problem geometry
#define IMG_H 512
#define IMG_W 512
#define NBATCH 32
#define CH_STRIDE (NBATCH * IMG_H * IMG_W)   // per-channel stride (elements)
#define B_STRIDE  (IMG_H * IMG_W)            // per-batch stride

// Tile geometry: 64 wide x 32 high output tile, +1 halo each side.
#define TW 64
#define TH 32
#define TROWS (TH + 2)      // 34
#define TCOLS (TW + 2)      // 66 valid columns
#define PITCH2 68           // row pitch in half2 elements (272 B, 16B-aligned rows)
#define FEL (TROWS * PITCH2)  // 2312 half2 per packed field-pair
// smem: 5 packed field-pairs x 2312 x 4B = 46240 B (static, < 48KB)

// Paired weights: 6 passes x 9 taps. Pass layout (loKernel, hiKernel):
//   0:(K0,K4) 1:(K6,K10) 2:(K2,K8) 3:(K1,K3) 4:(K5,K7) 5:(K9,K11)
__device__   float2 w2g[54];   // scratch written by prep kernel
__constant__ float2 cw2[54];   // constant copy used by main kernel

__global__ void prep_weights(const float* __restrict__ ker) {
    int t = threadIdx.x;
    if (t < 54) {
        const int A[6] = {0, 6, 2, 1, 5, 9};
        const int B[6] = {4, 10, 8, 3, 7, 11};
        int p = t / 9, k = t - p * 9;
        w2g[t] = make_float2(ker[A[p] * 9 + k], ker[B[p] * 9 + k]);
    }
}

// Packed fp32 FMA (sm_103a native f32x2 pipe).
__device__ __forceinline__ float2 fma2(float2 a, float2 b, float2 c) {
    float2 d;
    asm("fma.rn.f32x2 %0, %1, %2, %3;"
        : "=l"(*reinterpret_cast<unsigned long long*>(&d))
        : "l"(*reinterpret_cast<unsigned long long*>(&a)),
          "l"(*reinterpret_cast<unsigned long long*>(&b)),
          "l"(*reinterpret_cast<unsigned long long*>(&c)));
    return d;
}

// cbrt via MUFU lg2/ex2: x >= 0 always here (uniform [0,1) inputs).
// x==0: lg2 -> -inf, ex2(-inf) -> 0. Rel err ~1e-6, fine for 1e-3 gate.
__device__ __forceinline__ float cbrt_fast(float x) {
    float lg;
    asm("lg2.approx.f32 %0, %1;" : "=f"(lg) : "f"(x));
    float e = lg * 0.33333333333333f;
    float r;
    asm("ex2.approx.f32 %0, %1;" : "=f"(r) : "f"(e));
    return r;
}

// Load one window row: 6 channel-pair pixels stored as half2, unpack to float2.
// Row start is 16B aligned -> one LDS.128 + one LDS.64.
__device__ __forceinline__ void ldrow16(const __half2* __restrict__ row, float2 v[6]) {
    const uint4 a = *reinterpret_cast<const uint4*>(row);      // pixels 0..3
    const uint2 b = *reinterpret_cast<const uint2*>(row + 4);  // pixels 4..5
    v[0] = __half22float2(*reinterpret_cast<const __half2*>(&a.x));
    v[1] = __half22float2(*reinterpret_cast<const __half2*>(&a.y));
    v[2] = __half22float2(*reinterpret_cast<const __half2*>(&a.z));
    v[3] = __half22float2(*reinterpret_cast<const __half2*>(&a.w));
    v[4] = __half22float2(*reinterpret_cast<const __half2*>(&b.x));
    v[5] = __half22float2(*reinterpret_cast<const __half2*>(&b.y));
}

// Packed 3x3 conv over a 4-wide x 2-HIGH block: one weight-pair set.
// Window = 4 rows x 6 pixel-pairs; output row oy uses window rows oy..oy+2.
__device__ __forceinline__ void convp(const __half2* __restrict__ A, int off2,
                                      const float2* __restrict__ wp,
                                      float2 acc[2][4]) {
    #pragma unroll
    for (int r = 0; r < 4; r++) {
        float2 v[6];
        ldrow16(A + off2 + r * PITCH2, v);
        #pragma unroll
        for (int oy = 0; oy < 2; oy++) {
            const int dy = r - oy;
            if (dy >= 0 && dy < 3) {
                #pragma unroll
                for (int k = 0; k < 3; k++) {
                    const float2 w = wp[dy * 3 + k];
                    #pragma unroll
                    for (int ox = 0; ox < 4; ox++)
                        acc[oy][ox] = fma2(v[ox + k], w, acc[oy][ox]);
                }
            }
        }
    }
}

// Same window, two weight-pair sets sharing the row loads.
__device__ __forceinline__ void convpp(const __half2* __restrict__ A, int off2,
                                       const float2* __restrict__ wpA,
                                       const float2* __restrict__ wpB,
                                       float2 accA[2][4], float2 accB[2][4]) {
    #pragma unroll
    for (int r = 0; r < 4; r++) {
        float2 v[6];
        ldrow16(A + off2 + r * PITCH2, v);
        #pragma unroll
        for (int oy = 0; oy < 2; oy++) {
            const int dy = r - oy;
            if (dy >= 0 && dy < 3) {
                #pragma unroll
                for (int k = 0; k < 3; k++) {
                    const float2 wa = wpA[dy * 3 + k];
                    const float2 wb = wpB[dy * 3 + k];
                    #pragma unroll
                    for (int ox = 0; ox < 4; ox++) {
                        accA[oy][ox] = fma2(v[ox + k], wa, accA[oy][ox]);
                        accB[oy][ox] = fma2(v[ox + k], wb, accB[oy][ox]);
                    }
                }
            }
        }
    }
}

__global__ __launch_bounds__(256, 4)
void fused_bleed(const float* __restrict__ src, float* __restrict__ out) {
    __shared__ __align__(16) __half2 sm2[5 * FEL];

    const int tid = threadIdx.x;
    const int x0 = blockIdx.x * TW;
    const int y0 = blockIdx.y * TH;
    const int b  = blockIdx.z;

    const float* base = src + b * B_STRIDE;

    // ---- Load halo tiles; build 5 packed (channel-pair) fields in fp16.
    // inter(i,j) = (s_j^0.5 * s_i)^(2/3) = cbrt(s_j) * cbrt(s_i)^2
    for (int idx = tid; idx < TROWS * TCOLS; idx += 256) {
        const int ly = idx / TCOLS;
        const int lx = idx - ly * TCOLS;
        const int gy = y0 - 1 + ly;
        const int gx = x0 - 1 + lx;
        float s0 = 0.f, s1 = 0.f, s2 = 0.f, s3 = 0.f;
        if ((unsigned)gy < (unsigned)IMG_H && (unsigned)gx < (unsigned)IMG_W) {
            const int g = gy * IMG_W + gx;
            s0 = base[g];
            s1 = base[g + CH_STRIDE];
            s2 = base[g + 2 * CH_STRIDE];
            s3 = base[g + 3 * CH_STRIDE];
        }
        const float c0 = cbrt_fast(s0), c1 = cbrt_fast(s1);
        const float c2 = cbrt_fast(s2), c3 = cbrt_fast(s3);
        const float q0 = c0 * c0, q1 = c1 * c1, q2 = c2 * c2, q3 = c3 * c3;
        const int o = ly * PITCH2 + lx;
        sm2[o]           = __floats2half2_rn(s1, s2);            // passes 0,1
        sm2[o + FEL]     = __floats2half2_rn(s0, s3);            // pass 2
        sm2[o + 2 * FEL] = __floats2half2_rn(c1 * q0, c0 * q1);  // (f0,f1) pass 3
        sm2[o + 3 * FEL] = __floats2half2_rn(c2 * q1, c1 * q2);  // (f2,f3) pass 4
        sm2[o + 4 * FEL] = __floats2half2_rn(c3 * q2, c2 * q3);  // (f4,f5) pass 5
    }
    __syncthreads();

    // ---- Compute: each thread owns a 4-wide x 2-high block, all 4 channels.
    const int tx = tid & 15;            // column block (x4)
    const int ty = tid >> 4;            // output row pair (x2)
    const int off2 = (2 * ty) * PITCH2 + tx * 4;   // window top-left (half2 units)

    float2 P01[2][4] = {}, P12[2][4] = {}, P23[2][4] = {};  // (o0,o1),(o1,o2),(o2,o3)

    convpp(sm2,           off2, cw2, cw2 + 9, P01, P23);   // (s1,s2): K0/K4, K6/K10
    convp (sm2 + FEL,     off2, cw2 + 18, P12);            // (s0,s3): K2,K8
    convp (sm2 + 2 * FEL, off2, cw2 + 27, P01);            // (f0,f1): K1,K3
    convp (sm2 + 3 * FEL, off2, cw2 + 36, P12);            // (f2,f3): K5,K7
    convp (sm2 + 4 * FEL, off2, cw2 + 45, P23);            // (f4,f5): K9,K11

    // Exact fp32 centers straight from gmem (coalesced float4, hot in L2).
    #pragma unroll
    for (int oy = 0; oy < 2; oy++) {
        const int row = y0 + 2 * ty + oy;
        const float* sp = base + row * IMG_W + (x0 + tx * 4);
        const float4 s0v = *reinterpret_cast<const float4*>(sp);
        const float4 s1v = *reinterpret_cast<const float4*>(sp + CH_STRIDE);
        const float4 s2v = *reinterpret_cast<const float4*>(sp + 2 * CH_STRIDE);
        const float4 s3v = *reinterpret_cast<const float4*>(sp + 3 * CH_STRIDE);

        // out0 = s0 - P01.lo ; out1 = s1 - P01.hi - P12.lo
        // out2 = s2 - P12.hi - P23.lo ; out3 = s3 - P23.hi
        float4 r0 = { s0v.x - P01[oy][0].x, s0v.y - P01[oy][1].x,
                      s0v.z - P01[oy][2].x, s0v.w - P01[oy][3].x };
        float4 r1 = { s1v.x - P01[oy][0].y - P12[oy][0].x,
                      s1v.y - P01[oy][1].y - P12[oy][1].x,
                      s1v.z - P01[oy][2].y - P12[oy][2].x,
                      s1v.w - P01[oy][3].y - P12[oy][3].x };
        float4 r2 = { s2v.x - P12[oy][0].y - P23[oy][0].x,
                      s2v.y - P12[oy][1].y - P23[oy][1].x,
                      s2v.z - P12[oy][2].y - P23[oy][2].x,
                      s2v.w - P12[oy][3].y - P23[oy][3].x };
        float4 r3 = { s3v.x - P23[oy][0].y, s3v.y - P23[oy][1].y,
                      s3v.z - P23[oy][2].y, s3v.w - P23[oy][3].y };

        float* outp = out + b * B_STRIDE + row * IMG_W + (x0 + tx * 4);
        *reinterpret_cast<float4*>(outp)                  = r0;
        *reinterpret_cast<float4*>(outp + CH_STRIDE)      = r1;
        *reinterpret_cast<float4*>(outp + 2 * CH_STRIDE)  = r2;
        *reinterpret_cast<float4*>(outp + 3 * CH_STRIDE)  = r3;
    }
}

extern "C" void kernel_launch(void* const* d_in, const int* in_sizes, int n_in,
                              void* d_out, int out_size) {
    const float* src = (const float*)d_in[0];   // sources (4,32,512,512,1) fp32
    const float* ker = (const float*)d_in[1];   // kernels (12,3,3) fp32
    float* out = (float*)d_out;

    // Build paired weights on device, then copy into constant memory.
    // All graph-capturable: kernel node + D2D memcpy node.
    prep_weights<<<1, 64>>>(ker);
    void* w2addr = nullptr;
    cudaGetSymbolAddress(&w2addr, w2g);
    cudaMemcpyToSymbolAsync(cw2, w2addr, 54 * sizeof(float2), 0,
                            cudaMemcpyDeviceToDevice, 0);

    dim3 grid(IMG_W / TW, IMG_H / TH, NBATCH);  // (8, 16, 32)
    fused_bleed<<<grid, 256>>>(src, out);
}

// round 17
// speedup vs baseline: 1.1095x; 1.1095x over previous
#include <cuda_runtime.h>
#include <cuda_fp16.h>

// Problem geometry
#define IMG_H 512
#define IMG_W 512
#define NBATCH 32
#define CH_STRIDE (NBATCH * IMG_H * IMG_W)   // per-channel stride (elements)
#define B_STRIDE  (IMG_H * IMG_W)            // per-batch stride

// Tile geometry: 64 wide x 16 high output tile, +1 halo each side.
#define TW 64
#define TH 16
#define TROWS (TH + 2)      // 18
#define TCOLS (TW + 2)      // 66 valid columns
#define PITCH2 68           // row pitch in half2 elements (272 B, 16B-aligned rows)
#define FEL (TROWS * PITCH2)  // 1224 half2 per packed field-pair
// smem: 5 packed field-pairs x 1224 x 4B = 24480 B -> 6 CTAs = 146.9 KB/SM (fits 228K)

// Paired weights: 6 passes x 9 taps. Pass layout (loKernel, hiKernel):
//   0:(K0,K4) 1:(K6,K10) 2:(K2,K8) 3:(K1,K3) 4:(K5,K7) 5:(K9,K11)
__device__   float2 w2g[54];   // scratch written by prep kernel
__constant__ float2 cw2[54];   // constant copy used by main kernel

__global__ void prep_weights(const float* __restrict__ ker) {
    int t = threadIdx.x;
    if (t < 54) {
        const int A[6] = {0, 6, 2, 1, 5, 9};
        const int B[6] = {4, 10, 8, 3, 7, 11};
        int p = t / 9, k = t - p * 9;
        w2g[t] = make_float2(ker[A[p] * 9 + k], ker[B[p] * 9 + k]);
    }
}

// Packed fp32 FMA (sm_103a native f32x2 pipe).
__device__ __forceinline__ float2 fma2(float2 a, float2 b, float2 c) {
    float2 d;
    asm("fma.rn.f32x2 %0, %1, %2, %3;"
        : "=l"(*reinterpret_cast<unsigned long long*>(&d))
        : "l"(*reinterpret_cast<unsigned long long*>(&a)),
          "l"(*reinterpret_cast<unsigned long long*>(&b)),
          "l"(*reinterpret_cast<unsigned long long*>(&c)));
    return d;
}

// cbrt via MUFU lg2/ex2: x >= 0 always here (uniform [0,1) inputs).
// x==0: lg2 -> -inf, ex2(-inf) -> 0. Rel err ~1e-6, fine for 1e-3 gate.
__device__ __forceinline__ float cbrt_fast(float x) {
    float lg;
    asm("lg2.approx.f32 %0, %1;" : "=f"(lg) : "f"(x));
    float e = lg * 0.33333333333333f;
    float r;
    asm("ex2.approx.f32 %0, %1;" : "=f"(r) : "f"(e));
    return r;
}

// Load one window row: 6 channel-pair pixels stored as half2, unpack to float2.
// Row start is 16B aligned -> one LDS.128 + one LDS.64.
__device__ __forceinline__ void ldrow16(const __half2* __restrict__ row, float2 v[6]) {
    const uint4 a = *reinterpret_cast<const uint4*>(row);      // pixels 0..3
    const uint2 b = *reinterpret_cast<const uint2*>(row + 4);  // pixels 4..5
    v[0] = __half22float2(*reinterpret_cast<const __half2*>(&a.x));
    v[1] = __half22float2(*reinterpret_cast<const __half2*>(&a.y));
    v[2] = __half22float2(*reinterpret_cast<const __half2*>(&a.z));
    v[3] = __half22float2(*reinterpret_cast<const __half2*>(&a.w));
    v[4] = __half22float2(*reinterpret_cast<const __half2*>(&b.x));
    v[5] = __half22float2(*reinterpret_cast<const __half2*>(&b.y));
}

// Packed 3x3 conv over a 4-wide block: one weight-pair set.
__device__ __forceinline__ void convp(const __half2* __restrict__ A, int off2,
                                      const float2* __restrict__ wp, float2 acc[4]) {
    #pragma unroll
    for (int r = 0; r < 3; r++) {
        float2 v[6];
        ldrow16(A + off2 + r * PITCH2, v);
        #pragma unroll
        for (int k = 0; k < 3; k++) {
            const float2 w = wp[r * 3 + k];
            #pragma unroll
            for (int ox = 0; ox < 4; ox++)
                acc[ox] = fma2(v[ox + k], w, acc[ox]);
        }
    }
}

// Same window, two weight-pair sets sharing the row loads.
__device__ __forceinline__ void convpp(const __half2* __restrict__ A, int off2,
                                       const float2* __restrict__ wpA,
                                       const float2* __restrict__ wpB,
                                       float2 accA[4], float2 accB[4]) {
    #pragma unroll
    for (int r = 0; r < 3; r++) {
        float2 v[6];
        ldrow16(A + off2 + r * PITCH2, v);
        #pragma unroll
        for (int k = 0; k < 3; k++) {
            const float2 wa = wpA[r * 3 + k];
            const float2 wb = wpB[r * 3 + k];
            #pragma unroll
            for (int ox = 0; ox < 4; ox++) {
                accA[ox] = fma2(v[ox + k], wa, accA[ox]);
                accB[ox] = fma2(v[ox + k], wb, accB[ox]);
            }
        }
    }
}

__global__ __launch_bounds__(256, 6)
void fused_bleed(const float* __restrict__ src, float* __restrict__ out) {
    __shared__ __align__(16) __half2 sm2[5 * FEL];

    const int tid = threadIdx.x;
    const int x0 = blockIdx.x * TW;
    const int y0 = blockIdx.y * TH;
    const int b  = blockIdx.z;

    const float* base = src + b * B_STRIDE;

    // ---- Load halo tiles; build 5 packed (channel-pair) fields in fp16.
    // inter(i,j) = (s_j^0.5 * s_i)^(2/3) = cbrt(s_j) * cbrt(s_i)^2
    for (int idx = tid; idx < TROWS * TCOLS; idx += 256) {
        const int ly = idx / TCOLS;
        const int lx = idx - ly * TCOLS;
        const int gy = y0 - 1 + ly;
        const int gx = x0 - 1 + lx;
        float s0 = 0.f, s1 = 0.f, s2 = 0.f, s3 = 0.f;
        if ((unsigned)gy < (unsigned)IMG_H && (unsigned)gx < (unsigned)IMG_W) {
            const int g = gy * IMG_W + gx;
            s0 = base[g];
            s1 = base[g + CH_STRIDE];
            s2 = base[g + 2 * CH_STRIDE];
            s3 = base[g + 3 * CH_STRIDE];
        }
        const float c0 = cbrt_fast(s0), c1 = cbrt_fast(s1);
        const float c2 = cbrt_fast(s2), c3 = cbrt_fast(s3);
        const float q0 = c0 * c0, q1 = c1 * c1, q2 = c2 * c2, q3 = c3 * c3;
        const int o = ly * PITCH2 + lx;
        sm2[o]           = __floats2half2_rn(s1, s2);            // passes 0,1
        sm2[o + FEL]     = __floats2half2_rn(s0, s3);            // pass 2
        sm2[o + 2 * FEL] = __floats2half2_rn(c1 * q0, c0 * q1);  // (f0,f1) pass 3
        sm2[o + 3 * FEL] = __floats2half2_rn(c2 * q1, c1 * q2);  // (f2,f3) pass 4
        sm2[o + 4 * FEL] = __floats2half2_rn(c3 * q2, c2 * q3);  // (f4,f5) pass 5
    }
    __syncthreads();

    // ---- Compute: each thread owns a 4-wide x 1-high block, all 4 channels.
    const int tx = tid & 15;
    const int ty = tid >> 4;
    const int off2 = ty * PITCH2 + tx * 4;   // window top-left (half2 units, 16B aligned)

    float2 P01[4] = {}, P12[4] = {}, P23[4] = {};   // (o0,o1), (o1,o2), (o2,o3)

    convpp(sm2,           off2, cw2, cw2 + 9, P01, P23);   // (s1,s2): K0/K4, K6/K10
    convp (sm2 + FEL,     off2, cw2 + 18, P12);            // (s0,s3): K2,K8
    convp (sm2 + 2 * FEL, off2, cw2 + 27, P01);            // (f0,f1): K1,K3
    convp (sm2 + 3 * FEL, off2, cw2 + 36, P12);            // (f2,f3): K5,K7
    convp (sm2 + 4 * FEL, off2, cw2 + 45, P23);            // (f4,f5): K9,K11

    // Exact fp32 centers straight from gmem (coalesced float4, hot in L2).
    const float* sp = base + (y0 + ty) * IMG_W + (x0 + tx * 4);
    const float4 s0v = *reinterpret_cast<const float4*>(sp);
    const float4 s1v = *reinterpret_cast<const float4*>(sp + CH_STRIDE);
    const float4 s2v = *reinterpret_cast<const float4*>(sp + 2 * CH_STRIDE);
    const float4 s3v = *reinterpret_cast<const float4*>(sp + 3 * CH_STRIDE);

    // out0 = s0 - P01.lo ; out1 = s1 - P01.hi - P12.lo
    // out2 = s2 - P12.hi - P23.lo ; out3 = s3 - P23.hi
    float4 r0 = { s0v.x - P01[0].x, s0v.y - P01[1].x,
                  s0v.z - P01[2].x, s0v.w - P01[3].x };
    float4 r1 = { s1v.x - P01[0].y - P12[0].x, s1v.y - P01[1].y - P12[1].x,
                  s1v.z - P01[2].y - P12[2].x, s1v.w - P01[3].y - P12[3].x };
    float4 r2 = { s2v.x - P12[0].y - P23[0].x, s2v.y - P12[1].y - P23[1].x,
                  s2v.z - P12[2].y - P23[2].x, s2v.w - P12[3].y - P23[3].x };
    float4 r3 = { s3v.x - P23[0].y, s3v.y - P23[1].y,
                  s3v.z - P23[2].y, s3v.w - P23[3].y };

    float* outp = out + b * B_STRIDE + (y0 + ty) * IMG_W + (x0 + tx * 4);
    *reinterpret_cast<float4*>(outp)                  = r0;
    *reinterpret_cast<float4*>(outp + CH_STRIDE)      = r1;
    *reinterpret_cast<float4*>(outp + 2 * CH_STRIDE)  = r2;
    *reinterpret_cast<float4*>(outp + 3 * CH_STRIDE)  = r3;
}

extern "C" void kernel_launch(void* const* d_in, const int* in_sizes, int n_in,
                              void* d_out, int out_size) {
    const float* src = (const float*)d_in[0];   // sources (4,32,512,512,1) fp32
    const float* ker = (const float*)d_in[1];   // kernels (12,3,3) fp32
    float* out = (float*)d_out;

    // Build paired weights on device, then copy into constant memory.
    // All graph-capturable: kernel node + D2D memcpy node.
    prep_weights<<<1, 64>>>(ker);
    void* w2addr = nullptr;
    cudaGetSymbolAddress(&w2addr, w2g);
    cudaMemcpyToSymbolAsync(cw2, w2addr, 54 * sizeof(float2), 0,
                            cudaMemcpyDeviceToDevice, 0);

    dim3 grid(IMG_W / TW, IMG_H / TH, NBATCH);  // (8, 32, 32)
    fused_bleed<<<grid, 256>>>(src, out);
}